// round 10
// baseline (speedup 1.0000x reference)
#include <cuda_runtime.h>
#include <math.h>

#define T_DIM 32
#define B_DIM 16
#define S_DIM 128
#define D_DIM 1024

// Scratch (device globals: allocation-free per harness rules)
__device__ float g_pi[T_DIM * B_DIM * D_DIM];      // 2 MB  [T,B,D]
__device__ float g_pc[B_DIM * S_DIM * D_DIM];      // 8 MB  [B,S,D]
__device__ float g_scores[T_DIM * B_DIM * S_DIM];  // 256 KB [T,B,S]
__device__ float g_wh[2 * D_DIM * D_DIM];          // 8 MB  tf32-rounded W_in | W_ctx

// ===========================================================================
// Pass 0: round W_in / W_ctx to tf32 bits once (removes all B CVTs from GEMM)
// ===========================================================================
__device__ __forceinline__ unsigned round_tf32_bits(float f) {
    unsigned h;
    asm("cvt.rna.tf32.f32 %0, %1;" : "=r"(h) : "f"(f));
    return h;
}

__global__ __launch_bounds__(256)
void round_weights(const float* __restrict__ W_in, const float* __restrict__ W_ctx)
{
    const int i = blockIdx.x * 256 + threadIdx.x;          // float4 index
    float4 a = ((const float4*)W_in)[i];
    float4 b = ((const float4*)W_ctx)[i];
    float4 ra, rb;
    ra.x = __uint_as_float(round_tf32_bits(a.x));
    ra.y = __uint_as_float(round_tf32_bits(a.y));
    ra.z = __uint_as_float(round_tf32_bits(a.z));
    ra.w = __uint_as_float(round_tf32_bits(a.w));
    rb.x = __uint_as_float(round_tf32_bits(b.x));
    rb.y = __uint_as_float(round_tf32_bits(b.y));
    rb.z = __uint_as_float(round_tf32_bits(b.z));
    rb.w = __uint_as_float(round_tf32_bits(b.w));
    ((float4*)g_wh)[i]                   = ra;
    ((float4*)(g_wh + D_DIM * D_DIM))[i] = rb;
}

// ===========================================================================
// Tensor-core GEMM (NT): C[m,n] = sum_k A[m,k]*Wh[n,k] + bias[n]
// A = Ah + Al (exact tf32 2-term split in-kernel); B pre-rounded (pure LDS).
// Block tile 64x128, BK=16, 128 threads (4 warps, warp tile 32x64).
// cp.async 2-stage pipeline. Blocks [0,64): pi. Blocks [64,320): pc.
// ===========================================================================
#define GBM 64
#define GBN 128
#define GBK 16
#define GKPAD 20                 // 16+4: 80B rows (16B-aligned), conflict-free
#define PI_BLOCKS 64             // (512/64) * (1024/128)
#define PC_BLOCKS 256            // (2048/64) * (1024/128)
#define NKT (D_DIM / GBK)        // 64 k-tiles

__device__ __forceinline__ void cp16(void* smem, const void* g) {
    unsigned saddr = (unsigned)__cvta_generic_to_shared(smem);
    asm volatile("cp.async.cg.shared.global [%0], [%1], 16;" :: "r"(saddr), "l"(g));
}
__device__ __forceinline__ void split_tf32(float f, unsigned& hi, unsigned& lo) {
    asm("cvt.rna.tf32.f32 %0, %1;" : "=r"(hi) : "f"(f));
    float r = f - __uint_as_float(hi);
    asm("cvt.rna.tf32.f32 %0, %1;" : "=r"(lo) : "f"(r));
}
__device__ __forceinline__ void mma_tf32(float c[4], const unsigned a[4], const unsigned b[2]) {
    asm volatile(
        "mma.sync.aligned.m16n8k8.row.col.f32.tf32.tf32.f32 "
        "{%0,%1,%2,%3}, {%4,%5,%6,%7}, {%8,%9}, {%0,%1,%2,%3};"
        : "+f"(c[0]), "+f"(c[1]), "+f"(c[2]), "+f"(c[3])
        : "r"(a[0]), "r"(a[1]), "r"(a[2]), "r"(a[3]), "r"(b[0]), "r"(b[1]));
}

__global__ __launch_bounds__(128, 4)
void gemm_tc(const float* __restrict__ inputs, const float* __restrict__ b_in,
             const float* __restrict__ context, const float* __restrict__ b_ctx)
{
    __shared__ __align__(16) float As[2][GBM][GKPAD];   // 10.0 KB
    __shared__ __align__(16) float Bs[2][GBN][GKPAD];   // 20.0 KB

    const int bid = blockIdx.x;
    const float* A; const float* W; const float* bias; float* C;
    int bm, bn;
    if (bid < PI_BLOCKS) {
        A = inputs;  W = g_wh;                 bias = b_in;  C = g_pi;
        bm = (bid >> 3) * GBM;  bn = (bid & 7) * GBN;
    } else {
        const int b2 = bid - PI_BLOCKS;
        A = context; W = g_wh + D_DIM * D_DIM; bias = b_ctx; C = g_pc;
        bm = (b2 >> 3) * GBM;   bn = (b2 & 7) * GBN;
    }
    const int K = D_DIM, N = D_DIM;

    const int tid  = threadIdx.x;          // 128
    const int wid  = tid >> 5;             // 0..3
    const int lane = tid & 31;
    const int warp_m = (wid & 1) * 32;
    const int warp_n = (wid >> 1) * 64;
    const int lr = lane >> 2;              // 0..7
    const int lc = lane & 3;               // 0..3

    float acc[2][8][4];
    #pragma unroll
    for (int i = 0; i < 2; i++)
        #pragma unroll
        for (int j = 0; j < 8; j++)
            #pragma unroll
            for (int q = 0; q < 4; q++) acc[i][j][q] = 0.f;

    // A: 64x16 = 256 16B-chunks (2/thread). B: 128x16 = 512 chunks (4/thread).
    auto issue = [&](int kt, int buf) {
        const int k0 = kt * GBK;
        #pragma unroll
        for (int i = 0; i < 2; i++) {
            int id  = tid + i * 128;       // 0..255
            int row = id >> 2;             // 0..63
            int c4  = (id & 3) * 4;        // 0,4,8,12
            cp16(&As[buf][row][c4], A + (size_t)(bm + row) * K + k0 + c4);
        }
        #pragma unroll
        for (int i = 0; i < 4; i++) {
            int id  = tid + i * 128;       // 0..511
            int row = id >> 2;             // 0..127
            int c4  = (id & 3) * 4;
            cp16(&Bs[buf][row][c4], W + (size_t)(bn + row) * K + k0 + c4);
        }
        asm volatile("cp.async.commit_group;");
    };

    issue(0, 0);
    issue(1, 1);

    for (int kt = 0; kt < NKT; kt++) {
        if (kt < NKT - 1) asm volatile("cp.async.wait_group 1;");
        else              asm volatile("cp.async.wait_group 0;");
        __syncthreads();

        const int st = kt & 1;
        #pragma unroll
        for (int ka = 0; ka < 2; ka++) {
            const int k8 = ka * 8;
            // A fragments (2 m-atoms), exact hi/lo split
            unsigned ah[2][4], al[2][4];
            #pragma unroll
            for (int i = 0; i < 2; i++) {
                int r = warp_m + i * 16 + lr;
                split_tf32(As[st][r][k8 + lc],         ah[i][0], al[i][0]);
                split_tf32(As[st][r + 8][k8 + lc],     ah[i][1], al[i][1]);
                split_tf32(As[st][r][k8 + lc + 4],     ah[i][2], al[i][2]);
                split_tf32(As[st][r + 8][k8 + lc + 4], ah[i][3], al[i][3]);
            }
            // B fragments (8 n-atoms): pre-rounded, pure LDS
            unsigned bh[8][2];
            #pragma unroll
            for (int j = 0; j < 8; j++) {
                int n = warp_n + j * 8 + lr;
                bh[j][0] = __float_as_uint(Bs[st][n][k8 + lc]);
                bh[j][1] = __float_as_uint(Bs[st][n][k8 + lc + 4]);
            }
            #pragma unroll
            for (int i = 0; i < 2; i++)
                #pragma unroll
                for (int j = 0; j < 8; j++) {
                    mma_tf32(acc[i][j], ah[i], bh[j]);   // A_hi * B
                    mma_tf32(acc[i][j], al[i], bh[j]);   // A_lo * B
                }
        }
        __syncthreads();
        if (kt + 2 < NKT) issue(kt + 2, st);
    }

    // Epilogue
    #pragma unroll
    for (int i = 0; i < 2; i++) {
        int r0 = bm + warp_m + i * 16 + lr;
        #pragma unroll
        for (int j = 0; j < 8; j++) {
            int c0 = bn + warp_n + j * 8 + 2 * lc;
            float2 bv = *(const float2*)(bias + c0);
            float2 o0 = make_float2(acc[i][j][0] + bv.x, acc[i][j][1] + bv.y);
            float2 o1 = make_float2(acc[i][j][2] + bv.x, acc[i][j][3] + bv.y);
            *(float2*)(C + (size_t)r0 * N + c0)       = o0;
            *(float2*)(C + (size_t)(r0 + 8) * N + c0) = o1;
        }
    }
}

// ---------------------------------------------------------------------------
// scores[t,b,s] = sum_d swish(pi[t,b,d] + pc[b,s,d]) * w_one[d]
// sigmoid via MUFU.TANH: sigmoid(x) = 0.5*tanh(x/2) + 0.5
// ---------------------------------------------------------------------------
#define TT 16
#define SB 32
#define DC 128

__device__ __forceinline__ float fast_sigmoid(float x) {
    float h = 0.5f * x, t;
    asm("tanh.approx.f32 %0, %1;" : "=f"(t) : "f"(h));
    return fmaf(0.5f, t, 0.5f);
}

__global__ __launch_bounds__(256)
void scores_kernel(const float* __restrict__ w_one)
{
    __shared__ float sp[TT][DC + 1];
    __shared__ float sc[SB][DC + 1];
    __shared__ float sw[DC];

    const int b   = blockIdx.z;
    const int t0  = blockIdx.y * TT;
    const int s0  = blockIdx.x * SB;
    const int tid = threadIdx.x;
    const int tl  = tid >> 4;
    const int sl  = tid & 15;

    float acc0 = 0.f, acc1 = 0.f;

    for (int d0 = 0; d0 < D_DIM; d0 += DC) {
        #pragma unroll
        for (int i = 0; i < 2; i++) {
            int l = tid + i * 256;
            int row = l >> 5;
            int c = (l & 31) << 2;
            float4 v = *(const float4*)(g_pi +
                ((size_t)(t0 + row) * B_DIM + b) * D_DIM + d0 + c);
            sp[row][c] = v.x; sp[row][c + 1] = v.y;
            sp[row][c + 2] = v.z; sp[row][c + 3] = v.w;
        }
        #pragma unroll
        for (int i = 0; i < 4; i++) {
            int l = tid + i * 256;
            int row = l >> 5;
            int c = (l & 31) << 2;
            float4 v = *(const float4*)(g_pc +
                ((size_t)b * S_DIM + s0 + row) * D_DIM + d0 + c);
            sc[row][c] = v.x; sc[row][c + 1] = v.y;
            sc[row][c + 2] = v.z; sc[row][c + 3] = v.w;
        }
        if (tid < DC) sw[tid] = w_one[d0 + tid];
        __syncthreads();

        #pragma unroll 8
        for (int k = 0; k < DC; k++) {
            float w = sw[k];
            float p = sp[tl][k];
            float x0 = p + sc[sl][k];
            float x1 = p + sc[sl + 16][k];
            acc0 = fmaf(w * x0, fast_sigmoid(x0), acc0);
            acc1 = fmaf(w * x1, fast_sigmoid(x1), acc1);
        }
        __syncthreads();
    }

    g_scores[((size_t)(t0 + tl) * B_DIM + b) * S_DIM + s0 + sl]      = acc0;
    g_scores[((size_t)(t0 + tl) * B_DIM + b) * S_DIM + s0 + sl + 16] = acc1;
}

// ---------------------------------------------------------------------------
// Softmax over s + attn_context[t,b,d] = sum_s attn[t,b,s] * context[b,s,d]
// ---------------------------------------------------------------------------
__global__ __launch_bounds__(256)
void softmax_av_kernel(const float* __restrict__ context,
                       float* __restrict__ out_ctx,
                       float* __restrict__ out_attn)
{
    __shared__ float sat[T_DIM][S_DIM];
    __shared__ float sctx[64][128];

    const int dc  = blockIdx.x;
    const int b   = blockIdx.y;
    const int tid = threadIdx.x;

    #pragma unroll
    for (int i = 0; i < 16; i++) {
        int l = tid + i * 256;
        int t = l >> 7;
        int s = l & 127;
        sat[t][s] = g_scores[((size_t)t * B_DIM + b) * S_DIM + s];
    }
    __syncthreads();

    {
        int t = tid >> 3;
        int part = tid & 7;
        int sbase = part * 16;
        float m = -1e30f;
        #pragma unroll
        for (int i = 0; i < 16; i++) m = fmaxf(m, sat[t][sbase + i]);
        #pragma unroll
        for (int o = 4; o > 0; o >>= 1)
            m = fmaxf(m, __shfl_xor_sync(0xffffffffu, m, o, 8));
        float e[16];
        float sum = 0.f;
        #pragma unroll
        for (int i = 0; i < 16; i++) {
            e[i] = __expf(sat[t][sbase + i] - m);
            sum += e[i];
        }
        #pragma unroll
        for (int o = 4; o > 0; o >>= 1)
            sum += __shfl_xor_sync(0xffffffffu, sum, o, 8);
        float inv = __fdividef(1.f, sum);
        #pragma unroll
        for (int i = 0; i < 16; i++) sat[t][sbase + i] = e[i] * inv;
    }
    __syncthreads();

    if (dc == 0) {
        int t = tid >> 3;
        int sbase = (tid & 7) * 16;
        #pragma unroll
        for (int i = 0; i < 16; i++)
            out_attn[((size_t)t * B_DIM + b) * S_DIM + sbase + i] = sat[t][sbase + i];
    }

    const int t2 = tid >> 7;
    const int dl = tid & 127;
    float acc[16];
    #pragma unroll
    for (int i = 0; i < 16; i++) acc[i] = 0.f;

    for (int sc0 = 0; sc0 < S_DIM; sc0 += 64) {
        __syncthreads();
        #pragma unroll
        for (int i = 0; i < 8; i++) {
            int l = tid + i * 256;
            int row = l >> 5;
            int c = (l & 31) << 2;
            float4 v = *(const float4*)(context +
                ((size_t)b * S_DIM + sc0 + row) * D_DIM + dc * 128 + c);
            sctx[row][c] = v.x; sctx[row][c + 1] = v.y;
            sctx[row][c + 2] = v.z; sctx[row][c + 3] = v.w;
        }
        __syncthreads();

        for (int s = 0; s < 64; s++) {
            float cv = sctx[s][dl];
            #pragma unroll
            for (int i = 0; i < 16; i++)
                acc[i] = fmaf(sat[i * 2 + t2][sc0 + s], cv, acc[i]);
        }
    }

    #pragma unroll
    for (int i = 0; i < 16; i++) {
        out_ctx[((size_t)(i * 2 + t2) * B_DIM + b) * D_DIM + dc * 128 + dl] = acc[i];
    }
}

// ---------------------------------------------------------------------------
// Launch.  b_one skipped (softmax shift-invariant; scores not an output).
// ---------------------------------------------------------------------------
extern "C" void kernel_launch(void* const* d_in, const int* in_sizes, int n_in,
                              void* d_out, int out_size)
{
    const float* inputs  = (const float*)d_in[0];
    const float* context = (const float*)d_in[1];
    const float* W_in    = (const float*)d_in[2];
    const float* b_in    = (const float*)d_in[3];
    const float* W_ctx   = (const float*)d_in[4];
    const float* b_ctx   = (const float*)d_in[5];
    const float* w_one   = (const float*)d_in[6];

    float* out      = (float*)d_out;
    float* out_ctx  = out;                                   // [T,B,D]
    float* out_attn = out + (size_t)T_DIM * B_DIM * D_DIM;   // [T,B,S]

    // Pass 0: tf32-round both weight matrices (1M floats each, float4-wide)
    round_weights<<<(D_DIM * D_DIM / 4) / 256, 256>>>(W_in, W_ctx);
    // Fused pi + pc tensor-core GEMMs: 64 + 256 = 320 blocks
    gemm_tc<<<PI_BLOCKS + PC_BLOCKS, 128>>>(inputs, b_in, context, b_ctx);
    // scores
    {
        dim3 grid(S_DIM / SB, T_DIM / TT, B_DIM);            // 128 blocks
        scores_kernel<<<grid, 256>>>(w_one);
    }
    // softmax + AV
    {
        dim3 grid(D_DIM / 128, B_DIM);                       // 128 blocks
        softmax_av_kernel<<<grid, 256>>>(context, out_ctx, out_attn);
    }
}